// round 1
// baseline (speedup 1.0000x reference)
#include <cuda_runtime.h>

#define NB 32
#define HIDDEN 256
#define NQH 4
#define NKVH 2
#define HD 64
#define QKV_DIM 512
#define MAXS 8192
#define CHUNK 512
#define NCHUNK (MAXS / CHUNK)          // 16
#define NHEAD (NB * NQH)               // 128 q-head instances

// ---------------- scratch (device globals; no allocations allowed) ----------
__device__ float g_q[NB * HIDDEN];          // roped q, [b][hq][d]
__device__ float g_k[NB * NKVH * HD];       // roped new k
__device__ float g_v[NB * NKVH * HD];       // new v
__device__ float g_pm[NHEAD * NCHUNK];      // partial max
__device__ float g_pl[NHEAD * NCHUNK];      // partial sum
__device__ float g_pa[NHEAD * NCHUNK * HD]; // partial weighted-V acc
__device__ float g_ctx[NB * HIDDEN];        // attention context

// ---------------- kernel 1: qkv projection + rope ---------------------------
__global__ void __launch_bounds__(QKV_DIM) qkv_rope_kernel(
    const float* __restrict__ x, const int* __restrict__ ctx_len,
    const float* __restrict__ rope, const float* __restrict__ qkv_w,
    const float* __restrict__ qkv_b)
{
    int b = blockIdx.x, e = threadIdx.x;
    __shared__ float sx[HIDDEN];
    __shared__ float sq[QKV_DIM];
    if (e < HIDDEN) sx[e] = x[b * HIDDEN + e];
    __syncthreads();

    const float4* w4 = (const float4*)(qkv_w + (size_t)e * HIDDEN);
    float s = qkv_b[e];
#pragma unroll 16
    for (int j = 0; j < HIDDEN / 4; j++) {
        float4 w = w4[j];
        s += w.x * sx[4 * j] + w.y * sx[4 * j + 1] + w.z * sx[4 * j + 2] + w.w * sx[4 * j + 3];
    }
    sq[e] = s;
    __syncthreads();

    int pos = ctx_len[b];
    const float* cs = rope + (size_t)pos * HD;   // [0:32)=cos, [32:64)=sin

    if (e < HIDDEN + NKVH * HD) {
        // q or k: apply rope
        int d = e & 63, base = e & ~63;
        float val;
        if (d < 32)
            val = sq[base + d] * cs[d] - sq[base + d + 32] * cs[d + 32];
        else
            val = sq[base + d - 32] * cs[d] + sq[base + d] * cs[d - 32];
        if (e < HIDDEN) g_q[b * HIDDEN + e] = val;
        else            g_k[b * NKVH * HD + (e - HIDDEN)] = val;
    } else {
        g_v[b * NKVH * HD + (e - HIDDEN - NKVH * HD)] = s;  // v: no rope
    }
}

// ---------------- kernel 2: fused KV-cache copy + flash-decode partials -----
__global__ void __launch_bounds__(256) fused_attn_copy(
    const float* __restrict__ kv, const int* __restrict__ ctx_len,
    float* __restrict__ out)
{
    int blk   = blockIdx.x;
    int chunk = blk & (NCHUNK - 1);
    int h     = (blk >> 4) & (NKVH - 1);
    int b     = blk >> 5;
    int warp  = threadIdx.x >> 5, lane = threadIdx.x & 31;
    int pos   = ctx_len[b];

    // kv layout [b][t][h][m][d]
    size_t kb = (((size_t)b * 2 + 0) * NKVH + h) * (size_t)(MAXS * HD);
    size_t vb = kb + (size_t)NKVH * MAXS * HD;
    const float* kp  = kv + kb;
    const float* vp  = kv + vb;
    float* okp = out + NB * HIDDEN + kb;   // updated_kv starts after out[32,256]
    float* ovp = out + NB * HIDDEN + vb;

    int hq = h * 2;
    float2 q0 = *(const float2*)&g_q[((size_t)b * NQH + hq)     * HD + 2 * lane];
    float2 q1 = *(const float2*)&g_q[((size_t)b * NQH + hq + 1) * HD + 2 * lane];
    float2 kn = *(const float2*)&g_k[((size_t)b * NKVH + h) * HD + 2 * lane];
    float2 vn = *(const float2*)&g_v[((size_t)b * NKVH + h) * HD + 2 * lane];

    float m0 = -1e30f, l0 = 0.f, m1 = -1e30f, l1 = 0.f;
    float2 a0 = make_float2(0.f, 0.f), a1 = make_float2(0.f, 0.f);
    const float scale = 0.125f;   // 64^-0.5

    int row0 = chunk * CHUNK + warp * (CHUNK / 8);
#pragma unroll 2
    for (int i = 0; i < CHUNK / 8; i++) {
        int m = row0 + i;
        size_t off = (size_t)m * HD + 2 * lane;
        float2 kd, vd;
        if (m == pos) { kd = kn; vd = vn; }
        else          { kd = *(const float2*)(kp + off); vd = *(const float2*)(vp + off); }
        *(float2*)(okp + off) = kd;
        *(float2*)(ovp + off) = vd;

        if (m <= pos) {
            float p0 = kd.x * q0.x + kd.y * q0.y;
            float p1 = kd.x * q1.x + kd.y * q1.y;
#pragma unroll
            for (int sft = 16; sft > 0; sft >>= 1) {
                p0 += __shfl_xor_sync(0xffffffffu, p0, sft);
                p1 += __shfl_xor_sync(0xffffffffu, p1, sft);
            }
            p0 *= scale; p1 *= scale;
            float nm0 = fmaxf(m0, p0), nm1 = fmaxf(m1, p1);
            float f0 = __expf(m0 - nm0), w0 = __expf(p0 - nm0);
            float f1 = __expf(m1 - nm1), w1 = __expf(p1 - nm1);
            l0 = l0 * f0 + w0;  l1 = l1 * f1 + w1;
            a0.x = a0.x * f0 + w0 * vd.x;  a0.y = a0.y * f0 + w0 * vd.y;
            a1.x = a1.x * f1 + w1 * vd.x;  a1.y = a1.y * f1 + w1 * vd.y;
            m0 = nm0; m1 = nm1;
        }
    }

    // combine 8 warps -> one partial per CTA per grouped head
    __shared__ float sm[2][8], sl[2][8], sa[2][8][HD];
    if (lane == 0) { sm[0][warp] = m0; sl[0][warp] = l0; sm[1][warp] = m1; sl[1][warp] = l1; }
    sa[0][warp][2 * lane] = a0.x;  sa[0][warp][2 * lane + 1] = a0.y;
    sa[1][warp][2 * lane] = a1.x;  sa[1][warp][2 * lane + 1] = a1.y;
    __syncthreads();

    int t = threadIdx.x;
    if (t < 128) {
        int g = t >> 6, d = t & 63;
        float M = -1e30f;
#pragma unroll
        for (int w = 0; w < 8; w++) M = fmaxf(M, sm[g][w]);
        float L = 0.f, A = 0.f;
#pragma unroll
        for (int w = 0; w < 8; w++) {
            float e = __expf(sm[g][w] - M);
            L += sl[g][w] * e;
            A += sa[g][w][d] * e;
        }
        int head = (b * NKVH + h) * 2 + g;     // == b*4 + hq
        int pi = head * NCHUNK + chunk;
        if (d == 0) { g_pm[pi] = M; g_pl[pi] = L; }
        g_pa[(size_t)pi * HD + d] = A;
    }
}

// ---------------- kernel 3: combine chunk partials -> ctx -------------------
__global__ void __launch_bounds__(HD) combine_kernel()
{
    int head = blockIdx.x;   // b*4 + hq
    int d = threadIdx.x;
    float M = -1e30f;
#pragma unroll
    for (int c = 0; c < NCHUNK; c++) M = fmaxf(M, g_pm[head * NCHUNK + c]);
    float L = 0.f, A = 0.f;
#pragma unroll
    for (int c = 0; c < NCHUNK; c++) {
        float e = __expf(g_pm[head * NCHUNK + c] - M);
        L += g_pl[head * NCHUNK + c] * e;
        A += g_pa[(size_t)(head * NCHUNK + c) * HD + d] * e;
    }
    int b = head >> 2, hq = head & 3;
    g_ctx[b * HIDDEN + hq * HD + d] = A / L;
}

// ---------------- kernel 4: output projection -------------------------------
__global__ void __launch_bounds__(HIDDEN) outproj_kernel(
    const float* __restrict__ out_w, float* __restrict__ out)
{
    int b = blockIdx.x, e = threadIdx.x;
    __shared__ float sc[HIDDEN];
    sc[e] = g_ctx[b * HIDDEN + e];
    __syncthreads();
    const float4* w4 = (const float4*)(out_w + (size_t)e * HIDDEN);
    float s = 0.f;
#pragma unroll 16
    for (int j = 0; j < HIDDEN / 4; j++) {
        float4 w = w4[j];
        s += w.x * sc[4 * j] + w.y * sc[4 * j + 1] + w.z * sc[4 * j + 2] + w.w * sc[4 * j + 3];
    }
    out[b * HIDDEN + e] = s;
}

// ---------------- launch ----------------------------------------------------
extern "C" void kernel_launch(void* const* d_in, const int* in_sizes, int n_in,
                              void* d_out, int out_size)
{
    const float* x     = (const float*)d_in[0];
    const float* kv    = (const float*)d_in[1];
    const int*   ctx   = (const int*)d_in[2];
    const float* rope  = (const float*)d_in[3];
    const float* qkv_w = (const float*)d_in[4];
    const float* qkv_b = (const float*)d_in[5];
    const float* out_w = (const float*)d_in[6];
    float* out = (float*)d_out;

    qkv_rope_kernel<<<NB, QKV_DIM>>>(x, ctx, rope, qkv_w, qkv_b);
    fused_attn_copy<<<NB * NKVH * NCHUNK, 256>>>(kv, ctx, out);
    combine_kernel<<<NB * NQH, HD>>>();
    outproj_kernel<<<NB, HIDDEN>>>(out_w, out);
}

// round 2
// speedup vs baseline: 1.3609x; 1.3609x over previous
#include <cuda_runtime.h>

#define NB 32
#define HIDDEN 256
#define NQH 4
#define NKVH 2
#define HD 64
#define QKV_DIM 512
#define MAXS 8192
#define CHUNK 512
#define NCHUNK (MAXS / CHUNK)          // 16
#define NHEAD (NB * NQH)               // 128

// ---------------- scratch (device globals) ----------------------------------
__device__ float g_q[NB * HIDDEN];
__device__ float g_k[NB * NKVH * HD];
__device__ float g_v[NB * NKVH * HD];
__device__ float g_pm[NHEAD * NCHUNK];
__device__ float g_pl[NHEAD * NCHUNK];
__device__ float g_pa[NHEAD * NCHUNK * HD];
__device__ float g_ctx[NB * HIDDEN];

// ---------------- kernel 1: qkv projection + rope ---------------------------
// grid (2, NB), 256 threads: block x handles e in [x*256, x*256+256)
__global__ void __launch_bounds__(256) qkv_rope_kernel(
    const float* __restrict__ x, const int* __restrict__ ctx_len,
    const float* __restrict__ rope, const float* __restrict__ qkv_w,
    const float* __restrict__ qkv_b)
{
    int b = blockIdx.y, t = threadIdx.x;
    int e = blockIdx.x * 256 + t;
    __shared__ float sx[HIDDEN];
    __shared__ float sq[256];
    sx[t] = x[b * HIDDEN + t];
    __syncthreads();

    const float4* w4 = (const float4*)(qkv_w + (size_t)e * HIDDEN);
    float s = qkv_b[e];
#pragma unroll 16
    for (int j = 0; j < HIDDEN / 4; j++) {
        float4 w = w4[j];
        s += w.x * sx[4 * j] + w.y * sx[4 * j + 1] + w.z * sx[4 * j + 2] + w.w * sx[4 * j + 3];
    }
    sq[t] = s;
    __syncthreads();

    int pos = ctx_len[b];
    const float* cs = rope + (size_t)pos * HD;   // [0:32)=cos, [32:64)=sin

    if (e < HIDDEN + NKVH * HD) {
        int d = e & 63, base = t & ~63;   // pair lives inside this block's sq
        float val;
        if (d < 32)
            val = sq[base + d] * cs[d] - sq[base + d + 32] * cs[d + 32];
        else
            val = sq[base + d - 32] * cs[d] + sq[base + d] * cs[d - 32];
        if (e < HIDDEN) g_q[b * HIDDEN + e] = val;
        else            g_k[b * NKVH * HD + (e - HIDDEN)] = val;
    } else {
        g_v[b * NKVH * HD + (e - HIDDEN - NKVH * HD)] = s;
    }
}

// ---------------- kernel 2: fused KV-cache copy + flash-decode partials -----
// 1024 CTAs x 256 threads. Half-warp (16 lanes x float4) = one 64-float row.
__global__ void __launch_bounds__(256) fused_attn_copy(
    const float* __restrict__ kv, const int* __restrict__ ctx_len,
    float* __restrict__ out)
{
    int blk   = blockIdx.x;
    int chunk = blk & (NCHUNK - 1);
    int h     = (blk >> 4) & (NKVH - 1);
    int b     = blk >> 5;
    int warp  = threadIdx.x >> 5, lane = threadIdx.x & 31;
    int half  = lane >> 4, li = lane & 15;
    int pos   = ctx_len[b];

    size_t kb = (((size_t)b * 2 + 0) * NKVH + h) * (size_t)(MAXS * HD);
    size_t vb = kb + (size_t)NKVH * MAXS * HD;
    const float4* kp4 = (const float4*)(kv + kb);
    const float4* vp4 = (const float4*)(kv + vb);
    float4* okp4 = (float4*)(out + NB * HIDDEN + kb);
    float4* ovp4 = (float4*)(out + NB * HIDDEN + vb);

    int hq = h * 2;
    int d4 = li * 4;
    float4 q0 = *(const float4*)&g_q[((size_t)b * NQH + hq)     * HD + d4];
    float4 q1 = *(const float4*)&g_q[((size_t)b * NQH + hq + 1) * HD + d4];
    float4 kn = *(const float4*)&g_k[((size_t)b * NKVH + h) * HD + d4];
    float4 vn = *(const float4*)&g_v[((size_t)b * NKVH + h) * HD + d4];

    float m0 = -1e30f, l0 = 0.f, m1 = -1e30f, l1 = 0.f;
    float4 a0 = make_float4(0.f, 0.f, 0.f, 0.f);
    float4 a1 = make_float4(0.f, 0.f, 0.f, 0.f);
    const float scale = 0.125f;   // 64^-0.5

    int row0 = chunk * CHUNK + warp * (CHUNK / 8);
#pragma unroll 4
    for (int i = 0; i < CHUNK / 16; i++) {          // 2 rows per iter
        int m = row0 + 2 * i + half;                // per-half row
        size_t o4 = (size_t)m * (HD / 4) + li;
        float4 kd, vd;
        if (m == pos) { kd = kn; vd = vn; }
        else          { kd = __ldcs(kp4 + o4); vd = __ldcs(vp4 + o4); }
        __stcs(okp4 + o4, kd);
        __stcs(ovp4 + o4, vd);

        if (row0 + 2 * i <= pos) {                  // warp-uniform guard
            float p0 = kd.x * q0.x + kd.y * q0.y + kd.z * q0.z + kd.w * q0.w;
            float p1 = kd.x * q1.x + kd.y * q1.y + kd.z * q1.z + kd.w * q1.w;
#pragma unroll
            for (int sft = 8; sft > 0; sft >>= 1) { // stays within 16-lane half
                p0 += __shfl_xor_sync(0xffffffffu, p0, sft);
                p1 += __shfl_xor_sync(0xffffffffu, p1, sft);
            }
            if (m <= pos) {                          // per-half, ALU only
                p0 *= scale; p1 *= scale;
                float nm0 = fmaxf(m0, p0), nm1 = fmaxf(m1, p1);
                float f0 = __expf(m0 - nm0), w0 = __expf(p0 - nm0);
                float f1 = __expf(m1 - nm1), w1 = __expf(p1 - nm1);
                l0 = l0 * f0 + w0;  l1 = l1 * f1 + w1;
                a0.x = a0.x * f0 + w0 * vd.x;  a0.y = a0.y * f0 + w0 * vd.y;
                a0.z = a0.z * f0 + w0 * vd.z;  a0.w = a0.w * f0 + w0 * vd.w;
                a1.x = a1.x * f1 + w1 * vd.x;  a1.y = a1.y * f1 + w1 * vd.y;
                a1.z = a1.z * f1 + w1 * vd.z;  a1.w = a1.w * f1 + w1 * vd.w;
                m0 = nm0; m1 = nm1;
            }
        }
    }

    // merge the two half-warp softmax streams per head (shfl_xor 16)
    {
        float mo = __shfl_xor_sync(0xffffffffu, m0, 16);
        float lo = __shfl_xor_sync(0xffffffffu, l0, 16);
        float4 ao;
        ao.x = __shfl_xor_sync(0xffffffffu, a0.x, 16);
        ao.y = __shfl_xor_sync(0xffffffffu, a0.y, 16);
        ao.z = __shfl_xor_sync(0xffffffffu, a0.z, 16);
        ao.w = __shfl_xor_sync(0xffffffffu, a0.w, 16);
        float M = fmaxf(m0, mo);
        float e0 = __expf(m0 - M), e1 = __expf(mo - M);
        l0 = l0 * e0 + lo * e1;
        a0.x = a0.x * e0 + ao.x * e1;  a0.y = a0.y * e0 + ao.y * e1;
        a0.z = a0.z * e0 + ao.z * e1;  a0.w = a0.w * e0 + ao.w * e1;
        m0 = M;
    }
    {
        float mo = __shfl_xor_sync(0xffffffffu, m1, 16);
        float lo = __shfl_xor_sync(0xffffffffu, l1, 16);
        float4 ao;
        ao.x = __shfl_xor_sync(0xffffffffu, a1.x, 16);
        ao.y = __shfl_xor_sync(0xffffffffu, a1.y, 16);
        ao.z = __shfl_xor_sync(0xffffffffu, a1.z, 16);
        ao.w = __shfl_xor_sync(0xffffffffu, a1.w, 16);
        float M = fmaxf(m1, mo);
        float e0 = __expf(m1 - M), e1 = __expf(mo - M);
        l1 = l1 * e0 + lo * e1;
        a1.x = a1.x * e0 + ao.x * e1;  a1.y = a1.y * e0 + ao.y * e1;
        a1.z = a1.z * e0 + ao.z * e1;  a1.w = a1.w * e0 + ao.w * e1;
        m1 = M;
    }

    // cross-warp combine
    __shared__ float sm[2][8], sl[2][8], sa[2][8][HD];
    if (lane == 0) { sm[0][warp] = m0; sl[0][warp] = l0; sm[1][warp] = m1; sl[1][warp] = l1; }
    if (half == 0) {
        *(float4*)&sa[0][warp][d4] = a0;
        *(float4*)&sa[1][warp][d4] = a1;
    }
    __syncthreads();

    int t = threadIdx.x;
    if (t < 128) {
        int g = t >> 6, d = t & 63;
        float M = -1e30f;
#pragma unroll
        for (int w = 0; w < 8; w++) M = fmaxf(M, sm[g][w]);
        float L = 0.f, A = 0.f;
#pragma unroll
        for (int w = 0; w < 8; w++) {
            float e = __expf(sm[g][w] - M);
            L += sl[g][w] * e;
            A += sa[g][w][d] * e;
        }
        int head = (b * NKVH + h) * 2 + g;
        int pi = head * NCHUNK + chunk;
        if (d == 0) { g_pm[pi] = M; g_pl[pi] = L; }
        g_pa[(size_t)pi * HD + d] = A;
    }
}

// ---------------- kernel 3: combine chunk partials -> ctx -------------------
__global__ void __launch_bounds__(HD) combine_kernel()
{
    int head = blockIdx.x;
    int d = threadIdx.x;
    float M = -1e30f;
#pragma unroll
    for (int c = 0; c < NCHUNK; c++) M = fmaxf(M, g_pm[head * NCHUNK + c]);
    float L = 0.f, A = 0.f;
#pragma unroll
    for (int c = 0; c < NCHUNK; c++) {
        float e = __expf(g_pm[head * NCHUNK + c] - M);
        L += g_pl[head * NCHUNK + c] * e;
        A += g_pa[(size_t)(head * NCHUNK + c) * HD + d] * e;
    }
    int b = head >> 2, hq = head & 3;
    g_ctx[b * HIDDEN + hq * HD + d] = A / L;
}

// ---------------- kernel 4: output projection -------------------------------
// grid (4, NB), 256 threads: 4 threads per output element, 64 d each
__global__ void __launch_bounds__(256) outproj_kernel(
    const float* __restrict__ out_w, float* __restrict__ out)
{
    int b = blockIdx.y, t = threadIdx.x;
    __shared__ float sc[HIDDEN];
    sc[t] = g_ctx[b * HIDDEN + t];
    __syncthreads();
    int e = blockIdx.x * 64 + (t >> 2);
    int part = t & 3;
    const float4* w4 = (const float4*)(out_w + (size_t)e * HIDDEN + part * 64);
    const float*  c  = sc + part * 64;
    float s = 0.f;
#pragma unroll
    for (int j = 0; j < 16; j++) {
        float4 w = w4[j];
        s += w.x * c[4 * j] + w.y * c[4 * j + 1] + w.z * c[4 * j + 2] + w.w * c[4 * j + 3];
    }
    s += __shfl_xor_sync(0xffffffffu, s, 1);
    s += __shfl_xor_sync(0xffffffffu, s, 2);
    if (part == 0) out[b * HIDDEN + e] = s;
}

// ---------------- launch ----------------------------------------------------
extern "C" void kernel_launch(void* const* d_in, const int* in_sizes, int n_in,
                              void* d_out, int out_size)
{
    const float* x     = (const float*)d_in[0];
    const float* kv    = (const float*)d_in[1];
    const int*   ctx   = (const int*)d_in[2];
    const float* rope  = (const float*)d_in[3];
    const float* qkv_w = (const float*)d_in[4];
    const float* qkv_b = (const float*)d_in[5];
    const float* out_w = (const float*)d_in[6];
    float* out = (float*)d_out;

    qkv_rope_kernel<<<dim3(2, NB), 256>>>(x, ctx, rope, qkv_w, qkv_b);
    fused_attn_copy<<<NB * NKVH * NCHUNK, 256>>>(kv, ctx, out);
    combine_kernel<<<NB * NQH, HD>>>();
    outproj_kernel<<<dim3(4, NB), 256>>>(out_w, out);
}

// round 3
// speedup vs baseline: 1.4129x; 1.0381x over previous
#include <cuda_runtime.h>

#define NB 32
#define HIDDEN 256
#define NQH 4
#define NKVH 2
#define HD 64
#define QKV_DIM 512
#define MAXS 8192
#define CHUNK 512
#define NCHUNK (MAXS / CHUNK)          // 16
#define NHEAD (NB * NQH)               // 128

// ---------------- scratch (device globals) ----------------------------------
__device__ float g_q[NB * HIDDEN];
__device__ float g_k[NB * NKVH * HD];
__device__ float g_v[NB * NKVH * HD];
__device__ float g_pm[NHEAD * NCHUNK];
__device__ float g_pl[NHEAD * NCHUNK];
__device__ float g_pa[NHEAD * NCHUNK * HD];

// ---------------- kernel 1: qkv projection + rope ---------------------------
// grid (8, NB): block x owns one 64-wide "head" slice of the 512 qkv outputs.
// 256 threads: 4 threads per output element (64 inputs each), shfl-reduced.
__global__ void __launch_bounds__(256) qkv_rope_kernel(
    const float* __restrict__ x, const int* __restrict__ ctx_len,
    const float* __restrict__ rope, const float* __restrict__ qkv_w,
    const float* __restrict__ qkv_b)
{
    int b = blockIdx.y, hid = blockIdx.x, t = threadIdx.x;
    __shared__ float sx[HIDDEN];
    __shared__ float sq[HD];
    sx[t] = x[b * HIDDEN + t];
    __syncthreads();

    int d = t >> 2, part = t & 3;
    int e = hid * HD + d;
    const float4* w4 = (const float4*)(qkv_w + (size_t)e * HIDDEN + part * 64);
    const float*  c  = sx + part * 64;
    float s = 0.f;
#pragma unroll
    for (int j = 0; j < 16; j++) {
        float4 w = w4[j];
        s += w.x * c[4 * j] + w.y * c[4 * j + 1] + w.z * c[4 * j + 2] + w.w * c[4 * j + 3];
    }
    s += __shfl_xor_sync(0xffffffffu, s, 1);
    s += __shfl_xor_sync(0xffffffffu, s, 2);
    if (part == 0) sq[d] = s + qkv_b[e];
    __syncthreads();

    if (t < HD) {
        int pos = ctx_len[b];
        float val;
        if (hid < NQH + NKVH) {   // q or k: rope
            const float* cs = rope + (size_t)pos * HD;
            if (t < 32)
                val = sq[t] * cs[t] - sq[t + 32] * cs[t + 32];
            else
                val = sq[t - 32] * cs[t] + sq[t] * cs[t - 32];
        } else {
            val = sq[t];
        }
        if (hid < NQH)            g_q[b * HIDDEN + hid * HD + t] = val;
        else if (hid < NQH + NKVH) g_k[(b * NKVH + (hid - NQH)) * HD + t] = val;
        else                       g_v[(b * NKVH + (hid - NQH - NKVH)) * HD + t] = val;
    }
}

// ---------------- kernel 2: fused KV-cache copy + flash-decode partials -----
// 1024 CTAs x 256 threads. Half-warp (16 lanes x float4) = one 64-float row.
__global__ void __launch_bounds__(256) fused_attn_copy(
    const float* __restrict__ kv, const int* __restrict__ ctx_len,
    float* __restrict__ out)
{
    int blk   = blockIdx.x;
    int chunk = blk & (NCHUNK - 1);
    int h     = (blk >> 4) & (NKVH - 1);
    int b     = blk >> 5;
    int warp  = threadIdx.x >> 5, lane = threadIdx.x & 31;
    int half  = lane >> 4, li = lane & 15;
    int pos   = ctx_len[b];

    size_t kb = (((size_t)b * 2 + 0) * NKVH + h) * (size_t)(MAXS * HD);
    size_t vb = kb + (size_t)NKVH * MAXS * HD;
    const float4* kp4 = (const float4*)(kv + kb);
    const float4* vp4 = (const float4*)(kv + vb);
    float4* okp4 = (float4*)(out + NB * HIDDEN + kb);
    float4* ovp4 = (float4*)(out + NB * HIDDEN + vb);

    int hq = h * 2;
    int d4 = li * 4;
    float4 q0 = *(const float4*)&g_q[((size_t)b * NQH + hq)     * HD + d4];
    float4 q1 = *(const float4*)&g_q[((size_t)b * NQH + hq + 1) * HD + d4];
    float4 kn = *(const float4*)&g_k[((size_t)b * NKVH + h) * HD + d4];
    float4 vn = *(const float4*)&g_v[((size_t)b * NKVH + h) * HD + d4];

    float m0 = -1e30f, l0 = 0.f, m1 = -1e30f, l1 = 0.f;
    float4 a0 = make_float4(0.f, 0.f, 0.f, 0.f);
    float4 a1 = make_float4(0.f, 0.f, 0.f, 0.f);
    const float scale = 0.125f;   // 64^-0.5

    int row0 = chunk * CHUNK + warp * (CHUNK / 8);
#pragma unroll 8
    for (int i = 0; i < CHUNK / 16; i++) {          // 2 rows per iter
        int m = row0 + 2 * i + half;                // per-half row
        size_t o4 = (size_t)m * (HD / 4) + li;
        float4 kd, vd;
        if (m == pos) { kd = kn; vd = vn; }
        else          { kd = __ldcs(kp4 + o4); vd = __ldcs(vp4 + o4); }
        __stcs(okp4 + o4, kd);
        __stcs(ovp4 + o4, vd);

        if (row0 + 2 * i <= pos) {                  // warp-uniform guard
            float p0 = kd.x * q0.x + kd.y * q0.y + kd.z * q0.z + kd.w * q0.w;
            float p1 = kd.x * q1.x + kd.y * q1.y + kd.z * q1.z + kd.w * q1.w;
#pragma unroll
            for (int sft = 8; sft > 0; sft >>= 1) { // stays within 16-lane half
                p0 += __shfl_xor_sync(0xffffffffu, p0, sft);
                p1 += __shfl_xor_sync(0xffffffffu, p1, sft);
            }
            if (m <= pos) {                          // per-half, ALU only
                p0 *= scale; p1 *= scale;
                float nm0 = fmaxf(m0, p0), nm1 = fmaxf(m1, p1);
                float f0 = __expf(m0 - nm0), w0 = __expf(p0 - nm0);
                float f1 = __expf(m1 - nm1), w1 = __expf(p1 - nm1);
                l0 = l0 * f0 + w0;  l1 = l1 * f1 + w1;
                a0.x = a0.x * f0 + w0 * vd.x;  a0.y = a0.y * f0 + w0 * vd.y;
                a0.z = a0.z * f0 + w0 * vd.z;  a0.w = a0.w * f0 + w0 * vd.w;
                a1.x = a1.x * f1 + w1 * vd.x;  a1.y = a1.y * f1 + w1 * vd.y;
                a1.z = a1.z * f1 + w1 * vd.z;  a1.w = a1.w * f1 + w1 * vd.w;
                m0 = nm0; m1 = nm1;
            }
        }
    }

    // merge the two half-warp softmax streams per head (shfl_xor 16)
    {
        float mo = __shfl_xor_sync(0xffffffffu, m0, 16);
        float lo = __shfl_xor_sync(0xffffffffu, l0, 16);
        float4 ao;
        ao.x = __shfl_xor_sync(0xffffffffu, a0.x, 16);
        ao.y = __shfl_xor_sync(0xffffffffu, a0.y, 16);
        ao.z = __shfl_xor_sync(0xffffffffu, a0.z, 16);
        ao.w = __shfl_xor_sync(0xffffffffu, a0.w, 16);
        float M = fmaxf(m0, mo);
        float e0 = __expf(m0 - M), e1 = __expf(mo - M);
        l0 = l0 * e0 + lo * e1;
        a0.x = a0.x * e0 + ao.x * e1;  a0.y = a0.y * e0 + ao.y * e1;
        a0.z = a0.z * e0 + ao.z * e1;  a0.w = a0.w * e0 + ao.w * e1;
        m0 = M;
    }
    {
        float mo = __shfl_xor_sync(0xffffffffu, m1, 16);
        float lo = __shfl_xor_sync(0xffffffffu, l1, 16);
        float4 ao;
        ao.x = __shfl_xor_sync(0xffffffffu, a1.x, 16);
        ao.y = __shfl_xor_sync(0xffffffffu, a1.y, 16);
        ao.z = __shfl_xor_sync(0xffffffffu, a1.z, 16);
        ao.w = __shfl_xor_sync(0xffffffffu, a1.w, 16);
        float M = fmaxf(m1, mo);
        float e0 = __expf(m1 - M), e1 = __expf(mo - M);
        l1 = l1 * e0 + lo * e1;
        a1.x = a1.x * e0 + ao.x * e1;  a1.y = a1.y * e0 + ao.y * e1;
        a1.z = a1.z * e0 + ao.z * e1;  a1.w = a1.w * e0 + ao.w * e1;
        m1 = M;
    }

    // cross-warp combine
    __shared__ float sm[2][8], sl[2][8], sa[2][8][HD];
    if (lane == 0) { sm[0][warp] = m0; sl[0][warp] = l0; sm[1][warp] = m1; sl[1][warp] = l1; }
    if (half == 0) {
        *(float4*)&sa[0][warp][d4] = a0;
        *(float4*)&sa[1][warp][d4] = a1;
    }
    __syncthreads();

    int t = threadIdx.x;
    if (t < 128) {
        int g = t >> 6, d = t & 63;
        float M = -1e30f;
#pragma unroll
        for (int w = 0; w < 8; w++) M = fmaxf(M, sm[g][w]);
        float L = 0.f, A = 0.f;
#pragma unroll
        for (int w = 0; w < 8; w++) {
            float e = __expf(sm[g][w] - M);
            L += sl[g][w] * e;
            A += sa[g][w][d] * e;
        }
        int head = (b * NKVH + h) * 2 + g;
        int pi = head * NCHUNK + chunk;
        if (d == 0) { g_pm[pi] = M; g_pl[pi] = L; }
        g_pa[(size_t)pi * HD + d] = A;
    }
}

// ---------------- kernel 3: combine + output projection ---------------------
// grid (8, NB), 256 threads.
// Phase 1: every CTA (re)computes ctx[b] (256 values) into shared.
// Phase 2: CTA x computes outputs e in [x*32, x*32+32), 8 threads per output.
__global__ void __launch_bounds__(256) outproj_kernel(
    const float* __restrict__ out_w, float* __restrict__ out)
{
    int b = blockIdx.y, t = threadIdx.x;
    __shared__ float sc[HIDDEN];

    {   // phase 1: combine chunk partials -> ctx[b][t]
        int g = t >> 6, d = t & 63;
        int head = b * NQH + g;
        float M = -1e30f;
#pragma unroll
        for (int c = 0; c < NCHUNK; c++) M = fmaxf(M, g_pm[head * NCHUNK + c]);
        float L = 0.f, A = 0.f;
#pragma unroll
        for (int c = 0; c < NCHUNK; c++) {
            float e = __expf(g_pm[head * NCHUNK + c] - M);
            L += g_pl[head * NCHUNK + c] * e;
            A += g_pa[(size_t)(head * NCHUNK + c) * HD + d] * e;
        }
        sc[t] = A / L;
    }
    __syncthreads();

    // phase 2: projection, 8 threads per output element (32 inputs each)
    int e = blockIdx.x * 32 + (t >> 3);
    int part = t & 7;
    const float4* w4 = (const float4*)(out_w + (size_t)e * HIDDEN + part * 32);
    const float*  c  = sc + part * 32;
    float s = 0.f;
#pragma unroll
    for (int j = 0; j < 8; j++) {
        float4 w = w4[j];
        s += w.x * c[4 * j] + w.y * c[4 * j + 1] + w.z * c[4 * j + 2] + w.w * c[4 * j + 3];
    }
    s += __shfl_xor_sync(0xffffffffu, s, 1);
    s += __shfl_xor_sync(0xffffffffu, s, 2);
    s += __shfl_xor_sync(0xffffffffu, s, 4);
    if (part == 0) out[b * HIDDEN + e] = s;
}

// ---------------- launch ----------------------------------------------------
extern "C" void kernel_launch(void* const* d_in, const int* in_sizes, int n_in,
                              void* d_out, int out_size)
{
    const float* x     = (const float*)d_in[0];
    const float* kv    = (const float*)d_in[1];
    const int*   ctx   = (const int*)d_in[2];
    const float* rope  = (const float*)d_in[3];
    const float* qkv_w = (const float*)d_in[4];
    const float* qkv_b = (const float*)d_in[5];
    const float* out_w = (const float*)d_in[6];
    float* out = (float*)d_out;

    qkv_rope_kernel<<<dim3(8, NB), 256>>>(x, ctx, rope, qkv_w, qkv_b);
    fused_attn_copy<<<NB * NKVH * NCHUNK, 256>>>(kv, ctx, out);
    outproj_kernel<<<dim3(8, NB), 256>>>(out_w, out);
}